// round 2
// baseline (speedup 1.0000x reference)
#include <cuda_runtime.h>
#include <cuda_bf16.h>
#include <stdint.h>

#define NB 1024
#define NP 16
#define NE 3
#define NH 256
#define NL 4
#define NPAIR (NB*NP*NP)     // 262144
#define NBROWS (NB*NP)       // 16384

// -------------------- device scratch (no runtime allocation allowed) -----
__device__ __nv_bfloat16 g_W1t[6][256][256];   // [net][n][k]  (W1 transposed)
__device__ __nv_bfloat16 g_W2t[6][16][256];    // [net][n(pad16)][k]
__device__ float g_S[4][NPAIR][9];             // S tensors per layer
__device__ float g_bq[NBROWS][3];
__device__ float g_bp[NBROWS][3];

// -------------------- helpers --------------------------------------------
__device__ __forceinline__ float tanh_f32(float x) {
    float y; asm("tanh.approx.f32 %0, %1;" : "=f"(y) : "f"(x)); return y;
}
__device__ __forceinline__ uint32_t pack_bf16x2(float lo, float hi) {
    uint32_t r; asm("cvt.rn.bf16x2.f32 %0, %1, %2;" : "=r"(r) : "f"(hi), "f"(lo));
    return r;   // lo in lower 16 bits
}
__device__ __forceinline__ void ldsm4(uint32_t r[4], uint32_t addr) {
    asm volatile("ldmatrix.sync.aligned.m8n8.x4.shared.b16 {%0,%1,%2,%3}, [%4];"
        : "=r"(r[0]), "=r"(r[1]), "=r"(r[2]), "=r"(r[3]) : "r"(addr));
}
__device__ __forceinline__ void mma16816(float c[4],
    uint32_t a0, uint32_t a1, uint32_t a2, uint32_t a3,
    uint32_t b0, uint32_t b1) {
    asm volatile(
        "mma.sync.aligned.m16n8k16.row.col.f32.bf16.bf16.f32 "
        "{%0,%1,%2,%3},{%4,%5,%6,%7},{%8,%9},{%0,%1,%2,%3};"
        : "+f"(c[0]), "+f"(c[1]), "+f"(c[2]), "+f"(c[3])
        : "r"(a0), "r"(a1), "r"(a2), "r"(a3), "r"(b0), "r"(b1));
}

// -------------------- weight prep kernel ---------------------------------
__global__ void prep_kernel(const float* __restrict__ sW1,
                            const float* __restrict__ qW1,
                            const float* __restrict__ kW1,
                            const float* __restrict__ sW2,
                            const float* __restrict__ qW2,
                            const float* __restrict__ kW2) {
    int idx = blockIdx.x * blockDim.x + threadIdx.x;
    const int W1TOT = 6 * 256 * 256;
    if (idx < W1TOT) {
        int net = idx >> 16; int rem = idx & 65535;
        int n = rem >> 8; int k = rem & 255;
        const float* src = (net < 4) ? (sW1 + net * 65536)
                                     : ((net == 4) ? qW1 : kW1);
        g_W1t[net][n][k] = __float2bfloat16(src[k * 256 + n]);
    } else {
        int j = idx - W1TOT;
        if (j < 6 * 16 * 256) {
            int net = j / 4096; int rem = j & 4095;
            int n = rem >> 8; int k = rem & 255;
            float v = 0.f;
            if (net < 4)      { if (n < 9) v = sW2[net * 2304 + k * 9 + n]; }
            else if (net == 4){ if (n < 3) v = qW2[k * 3 + n]; }
            else              { if (n < 3) v = kW2[k * 3 + n]; }
            g_W2t[net][n][k] = __float2bfloat16(v);
        }
    }
}

// -------------------- fused MLP kernel ------------------------------------
// 256 threads = 8 warps. warp = nw*2 + mw. BM=64 rows/tile.
// GEMM1: H1[64,256] = tanh(h0[64,256] @ W1[256,256] + b1)   (bf16 HMMA)
// GEMM2: out[64,16] = tanh(H1 @ W2t^T + b2)  (A-frags direct from GEMM1 C-frags)
struct SmemLayout {
    __nv_bfloat16 W1t[256][264];   // [n][k] padded
    __nv_bfloat16 h0[64][264];     // [row][k] padded
    __nv_bfloat16 W2t[16][264];    // [n][k] padded
    float red[8][32][16];          // GEMM2 partials per warp
    float b1s[256];
    float b0s[256];
    float W0s[2][256];
    float b2s[16];
    float mjs[64];
    float mis[64];
};

__global__ void __launch_bounds__(256, 1) mlp_fused(
    const float* __restrict__ m,
    const float* __restrict__ W0_0, const float* __restrict__ b0_0,
    const float* __restrict__ b1_0, const float* __restrict__ b2_0,
    const float* __restrict__ W0_1, const float* __restrict__ b0_1,
    const float* __restrict__ b1_1, const float* __restrict__ b2_1,
    int net_base, int pair_mode, int ntiles, int out_valid)
{
    extern __shared__ char smem_raw[];
    SmemLayout& S = *reinterpret_cast<SmemLayout*>(smem_raw);
    const int t = threadIdx.x;
    const int warp = t >> 5, lane = t & 31;
    const int g = lane >> 2, tg = lane & 3;
    const int mw = warp & 1, nw = warp >> 1;
    const int y = blockIdx.y;
    const int net = net_base + y;

    const float *W0g, *b0g, *b1g, *b2g;
    float* op;
    if (pair_mode) {
        W0g = W0_0 + y * 2 * NH; b0g = b0_0 + y * NH;
        b1g = b1_0 + y * NH;     b2g = b2_0 + y * 9;
        op  = &g_S[y][0][0];
    } else {
        if (y == 0) { W0g = W0_0; b0g = b0_0; b1g = b1_0; b2g = b2_0; op = &g_bq[0][0]; }
        else        { W0g = W0_1; b0g = b0_1; b1g = b1_1; b2g = b2_1; op = &g_bp[0][0]; }
    }

    // ---- load weights to smem (once per block) ----
    {
        const uint4* src = reinterpret_cast<const uint4*>(&g_W1t[net][0][0]);
        for (int idx = t; idx < 256 * 32; idx += 256) {
            int n = idx >> 5, ch = idx & 31;
            *reinterpret_cast<uint4*>(&S.W1t[n][ch * 8]) = src[idx];
        }
        const uint4* src2 = reinterpret_cast<const uint4*>(&g_W2t[net][0][0]);
        for (int idx = t; idx < 16 * 32; idx += 256) {
            int n = idx >> 5, ch = idx & 31;
            *reinterpret_cast<uint4*>(&S.W2t[n][ch * 8]) = src2[idx];
        }
        S.b1s[t] = b1g[t];
        S.b0s[t] = b0g[t];
        S.W0s[0][t] = W0g[t];
        S.W0s[1][t] = pair_mode ? W0g[NH + t] : 0.f;
        if (t < 16) S.b2s[t] = (t < out_valid) ? b2g[t] : 0.f;
    }
    __syncthreads();

    const int a_r = (lane & 7) + ((lane & 8) ? 8 : 0);
    const int a_c = (lane & 16) ? 8 : 0;
    const uint32_t h0base = (uint32_t)__cvta_generic_to_shared(&S.h0[0][0]);

    for (int tile = blockIdx.x; tile < ntiles; tile += gridDim.x) {
        const int row0 = tile * 64;
        // ---- m values for this tile ----
        if (t < 64) {
            int rg = row0 + t;
            float xj, xi;
            if (pair_mode) {
                int b = rg >> 8, ij = rg & 255;
                int i = ij >> 4, j = ij & 15;
                xj = m[b * NP + j]; xi = m[b * NP + i];
            } else { xj = m[rg]; xi = 0.f; }
            S.mjs[t] = xj; S.mis[t] = xi;
        }
        __syncthreads();

        // ---- h0 = tanh(x @ W0 + b0) into smem (bf16) ----
        {
            int r = t >> 2, cb = (t & 3) * 64;
            float xj = S.mjs[r], xi = S.mis[r];
            #pragma unroll
            for (int k = 0; k < 64; k += 2) {
                int kk = cb + k;
                float a0 = fmaf(xj, S.W0s[0][kk],   fmaf(xi, S.W0s[1][kk],   S.b0s[kk]));
                float a1 = fmaf(xj, S.W0s[0][kk+1], fmaf(xi, S.W0s[1][kk+1], S.b0s[kk+1]));
                *reinterpret_cast<uint32_t*>(&S.h0[r][kk]) =
                    pack_bf16x2(tanh_f32(a0), tanh_f32(a1));
            }
        }
        __syncthreads();

        // ---- GEMM1: acc = h0 @ W1 (this warp: rows mw*32..+31, cols nw*64..+63)
        float acc[2][8][4];
        #pragma unroll
        for (int mt = 0; mt < 2; mt++)
            #pragma unroll
            for (int nt = 0; nt < 8; nt++)
                #pragma unroll
                for (int c = 0; c < 4; c++) acc[mt][nt][c] = 0.f;

        const int rbase = mw * 32;
        #pragma unroll 4
        for (int kt = 0; kt < 16; kt++) {
            uint32_t a[2][4];
            #pragma unroll
            for (int mt = 0; mt < 2; mt++) {
                uint32_t addr = h0base +
                    (uint32_t)(((rbase + mt * 16 + a_r) * 264 + kt * 16 + a_c) * 2);
                ldsm4(a[mt], addr);
            }
            #pragma unroll
            for (int nt = 0; nt < 8; nt++) {
                int n = nw * 64 + nt * 8 + g;
                uint32_t b0 = *reinterpret_cast<const uint32_t*>(&S.W1t[n][kt * 16 + 2 * tg]);
                uint32_t b1 = *reinterpret_cast<const uint32_t*>(&S.W1t[n][kt * 16 + 2 * tg + 8]);
                mma16816(acc[0][nt], a[0][0], a[0][1], a[0][2], a[0][3], b0, b1);
                mma16816(acc[1][nt], a[1][0], a[1][1], a[1][2], a[1][3], b0, b1);
            }
        }

        // ---- epilogue1: +b1, tanh, pack directly into GEMM2 A-fragments ----
        uint32_t A2[2][8][2];
        #pragma unroll
        for (int nt = 0; nt < 8; nt++) {
            int c0 = nw * 64 + nt * 8 + 2 * tg;
            float bb0 = S.b1s[c0], bb1 = S.b1s[c0 + 1];
            #pragma unroll
            for (int mt = 0; mt < 2; mt++) {
                float v0 = tanh_f32(acc[mt][nt][0] + bb0);
                float v1 = tanh_f32(acc[mt][nt][1] + bb1);
                float v2 = tanh_f32(acc[mt][nt][2] + bb0);
                float v3 = tanh_f32(acc[mt][nt][3] + bb1);
                A2[mt][nt][0] = pack_bf16x2(v0, v1);
                A2[mt][nt][1] = pack_bf16x2(v2, v3);
            }
        }

        // ---- GEMM2 (per-warp k-slice nw*64..+63, partial sums) ----
        float c2[2][2][4];
        #pragma unroll
        for (int mt = 0; mt < 2; mt++)
            #pragma unroll
            for (int nb = 0; nb < 2; nb++)
                #pragma unroll
                for (int c = 0; c < 4; c++) c2[mt][nb][c] = 0.f;

        #pragma unroll
        for (int kt2 = 0; kt2 < 4; kt2++) {
            #pragma unroll
            for (int mt = 0; mt < 2; mt++) {
                uint32_t a0 = A2[mt][2 * kt2][0],     a1 = A2[mt][2 * kt2][1];
                uint32_t a2 = A2[mt][2 * kt2 + 1][0], a3 = A2[mt][2 * kt2 + 1][1];
                #pragma unroll
                for (int nb = 0; nb < 2; nb++) {
                    uint32_t b0 = *reinterpret_cast<const uint32_t*>(
                        &S.W2t[nb * 8 + g][nw * 64 + kt2 * 16 + 2 * tg]);
                    uint32_t b1 = *reinterpret_cast<const uint32_t*>(
                        &S.W2t[nb * 8 + g][nw * 64 + kt2 * 16 + 2 * tg + 8]);
                    mma16816(c2[mt][nb], a0, a1, a2, a3, b0, b1);
                }
            }
        }

        // ---- stage partials ----
        #pragma unroll
        for (int mt = 0; mt < 2; mt++)
            #pragma unroll
            for (int nb = 0; nb < 2; nb++)
                #pragma unroll
                for (int c = 0; c < 4; c++) {
                    int rr = mt * 16 + g + ((c >> 1) & 1) * 8;
                    int cc = nb * 8 + 2 * tg + (c & 1);
                    S.red[warp][rr][cc] = c2[mt][nb][c];
                }
        __syncthreads();

        // ---- reduce over 4 k-slices, +b2, tanh, store ----
        {
            int r64 = t >> 2, cq = t & 3;
            int mw2 = r64 >> 5, r32 = r64 & 31;
            #pragma unroll
            for (int cc = 0; cc < 4; cc++) {
                int col = cq * 4 + cc;
                float s = S.b2s[col];
                #pragma unroll
                for (int nn = 0; nn < 4; nn++) s += S.red[nn * 2 + mw2][r32][col];
                s = tanh_f32(s);
                if (col < out_valid)
                    op[(size_t)(row0 + r64) * out_valid + col] = s;
            }
        }
        __syncthreads();
    }
}

// -------------------- final assembly: sequential symplectic updates -------
__global__ void __launch_bounds__(256) assemble_kernel(
    const float* __restrict__ q, const float* __restrict__ p,
    const float* __restrict__ dtp, float* __restrict__ out)
{
    __shared__ float qf[48], pf[48];
    __shared__ float Sc[256][9];
    int b = blockIdx.x, t = threadIdx.x;
    if (t < 48) { qf[t] = q[b * 48 + t]; pf[t] = p[b * 48 + t]; }
    float dt = dtp[0];
    float scale = dt * dt * dt;
    __syncthreads();

    #pragma unroll
    for (int l = 0; l < 4; l++) {
        #pragma unroll
        for (int c = 0; c < 9; c++) Sc[t][c] = g_S[l][b * 256 + t][c];
        __syncthreads();
        const float* src = (l & 1) ? pf : qf;
        float*       dst = (l & 1) ? qf : pf;
        if (t < 48) {
            int i = t / 3, a = t - (t / 3) * 3;
            float s = 0.f;
            // M part: M[(i,a),(j,c)] = S[b,i,j,a,c]
            #pragma unroll
            for (int j = 0; j < 16; j++)
                #pragma unroll
                for (int c = 0; c < 3; c++)
                    s += Sc[i * 16 + j][a * 3 + c] * src[j * 3 + c];
            // M^T part: (M^T)[(i,a),(j,c)] = S[b,j,i,c,a]
            #pragma unroll
            for (int ii = 0; ii < 16; ii++)
                #pragma unroll
                for (int aa = 0; aa < 3; aa++)
                    s += Sc[ii * 16 + i][aa * 3 + a] * src[ii * 3 + aa];
            dst[t] += s * scale;
        }
        __syncthreads();
    }

    if (t < 48) {
        int row = b * 16 + t / 3, e = t - (t / 3) * 3;
        out[b * 48 + t]           = qf[t] + g_bq[row][e] * scale;
        out[NB * 48 + b * 48 + t] = pf[t] + g_bp[row][e] * scale;
    }
}

// -------------------- launch ----------------------------------------------
extern "C" void kernel_launch(void* const* d_in, const int* in_sizes, int n_in,
                              void* d_out, int out_size) {
    const float* q   = (const float*)d_in[0];
    const float* p   = (const float*)d_in[1];
    const float* m   = (const float*)d_in[2];
    const float* dt  = (const float*)d_in[3];
    const float* sW0 = (const float*)d_in[4];
    const float* sb0 = (const float*)d_in[5];
    const float* sW1 = (const float*)d_in[6];
    const float* sb1 = (const float*)d_in[7];
    const float* sW2 = (const float*)d_in[8];
    const float* sb2 = (const float*)d_in[9];
    const float* qW0 = (const float*)d_in[10];
    const float* qb0 = (const float*)d_in[11];
    const float* qW1 = (const float*)d_in[12];
    const float* qb1 = (const float*)d_in[13];
    const float* qW2 = (const float*)d_in[14];
    const float* qb2 = (const float*)d_in[15];
    const float* kW0 = (const float*)d_in[16];
    const float* kb0 = (const float*)d_in[17];
    const float* kW1 = (const float*)d_in[18];
    const float* kb1 = (const float*)d_in[19];
    const float* kW2 = (const float*)d_in[20];
    const float* kb2 = (const float*)d_in[21];
    float* out = (float*)d_out;

    static bool attr_set = false;
    if (!attr_set) {
        cudaFuncSetAttribute(mlp_fused, cudaFuncAttributeMaxDynamicSharedMemorySize,
                             (int)sizeof(SmemLayout));
        attr_set = true;
    }

    // 1) weight prep (fp32 -> bf16, transposed)
    {
        int total = 6 * 256 * 256 + 6 * 16 * 256;
        prep_kernel<<<(total + 255) / 256, 256>>>(sW1, qW1, kW1, sW2, qW2, kW2);
    }
    // 2) pair MLPs: all 4 S layers in parallel (grid.y = layer)
    {
        dim3 grid(37, 4);
        mlp_fused<<<grid, 256, sizeof(SmemLayout)>>>(
            m, sW0, sb0, sb1, sb2,
            nullptr, nullptr, nullptr, nullptr,
            0, 1, NPAIR / 64, 9);
    }
    // 3) bias MLPs (q-net, k-net)
    {
        dim3 grid(74, 2);
        mlp_fused<<<grid, 256, sizeof(SmemLayout)>>>(
            m, qW0, qb0, qb1, qb2,
            kW0, kb0, kb1, kb2,
            4, 0, NBROWS / 64, 3);
    }
    // 4) assemble sequential symplectic updates + biases -> output
    assemble_kernel<<<NB, 256>>>(q, p, dt, out);
}